// round 14
// baseline (speedup 1.0000x reference)
#include <cuda_runtime.h>
#include <cuda_bf16.h>
#include <math.h>
#include <cstdint>

#define NN   100000
#define NE   640000
#define DD   128
#define NG   512
#define SCAN_B 1024
#define NSB  ((NN + SCAN_B - 1) / SCAN_B)   // 98 scan blocks
#define NTILES ((NN + 255) / 256)           // 391 (256 rows per CTA)

// ---------------- scratch (no allocations allowed) ----------------
__device__ uint2 g_hwb[(size_t)NN * 32];    // h@W in bf16x2 (25.6MB)
__device__ uint2 g_hbf[(size_t)NN * 32];    // relu(agg+b) in bf16x2 (25.6MB)
__device__ float g_dinv[NN];
__device__ float g_dinv2[NN];
__device__ int   g_cnt [NN];
__device__ int   g_off [NN + 1];
__device__ int   g_cursor[NN];
__device__ int   g_csrc[NE];
__device__ float g_cw  [NE];
__device__ int   g_bsum[NSB];
__device__ int   g_goff[NG + 1];            // per-graph node ranges (batch sorted)
// packed W fragments: [layer][n(128)][kk(8)][q(4)] uint4 = {hi@kb, hi@kb+4, lo@kb, lo@kb+4}
__device__ uint4 g_wpack[4 * 128 * 8 * 4];

// ---------------- smem layout for MMA GEMM ----------------
#define WPAD 36                          // uint4 per n-row in smem (padded from 32)
#define SMEM_MMA (128 * WPAD * 16)       // 73728

__device__ __forceinline__ void mma_bf16(float c[4], uint32_t a0, uint32_t a1,
                                         uint32_t a2, uint32_t a3,
                                         uint32_t b0, uint32_t b1) {
    asm volatile(
        "mma.sync.aligned.m16n8k16.row.col.f32.bf16.bf16.f32 "
        "{%0,%1,%2,%3}, {%4,%5,%6,%7}, {%8,%9}, {%0,%1,%2,%3};"
        : "+f"(c[0]), "+f"(c[1]), "+f"(c[2]), "+f"(c[3])
        : "r"(a0), "r"(a1), "r"(a2), "r"(a3), "r"(b0), "r"(b1));
}

__device__ __forceinline__ uint32_t bf2_of(float a, float b) {
    __nv_bfloat162 t = __float22bfloat162_rn(make_float2(a, b));
    return *reinterpret_cast<uint32_t*>(&t);
}
__device__ __forceinline__ float2 bf2f(uint32_t u) {
    __nv_bfloat162 h = *reinterpret_cast<__nv_bfloat162*>(&u);
    return __bfloat1622float2(h);
}

// ---------------- main-stream init: W pack ----------------
__global__ void k_wpack(const float* __restrict__ convW) {
    int idx = blockIdx.x * 256 + threadIdx.x;
    if (idx < 16384) {
        int q  = idx & 3;
        int kk = (idx >> 2) & 7;
        int n  = (idx >> 5) & 127;
        int l  = idx >> 12;
        int k0 = kk * 16 + q * 2;
        const float* Wl = convW + (size_t)l * 16384;
        float w00 = Wl[(size_t)(k0    ) * 128 + n], w01 = Wl[(size_t)(k0 + 1) * 128 + n];
        float w10 = Wl[(size_t)(k0 + 8) * 128 + n], w11 = Wl[(size_t)(k0 + 9) * 128 + n];
        __nv_bfloat162 h0 = __float22bfloat162_rn(make_float2(w00, w01));
        __nv_bfloat162 h1 = __float22bfloat162_rn(make_float2(w10, w11));
        float2 f0 = __bfloat1622float2(h0), f1 = __bfloat1622float2(h1);
        uint4 v;
        v.x = *reinterpret_cast<uint32_t*>(&h0);
        v.y = *reinterpret_cast<uint32_t*>(&h1);
        v.z = bf2_of(w00 - f0.x, w01 - f0.y);
        v.w = bf2_of(w10 - f1.x, w11 - f1.y);
        g_wpack[idx] = v;
    }
}

// ---------------- side-stream CSR build + graph offsets ----------------
__global__ void k_cntzero() {
    int n = blockIdx.x * blockDim.x + threadIdx.x;
    if (n < NN) g_cnt[n] = 0;
}
__global__ void k_cnt(const int* __restrict__ dst) {
    int e = blockIdx.x * blockDim.x + threadIdx.x;
    if (e < NE) atomicAdd(&g_cnt[dst[e]], 1);
}
// per-graph node ranges from sorted batch
__global__ void k_goff(const int* __restrict__ batch) {
    int n = blockIdx.x * blockDim.x + threadIdx.x;
    if (n > NN) return;
    int glo = (n == 0)  ? 0  : batch[n - 1] + 1;
    int ghi = (n == NN) ? NG : batch[n];
    for (int g = glo; g <= ghi; g++) g_goff[g] = n;
}
__global__ __launch_bounds__(SCAN_B) void k_scan1() {
    __shared__ int s[SCAN_B];
    int t = threadIdx.x;
    int i = blockIdx.x * SCAN_B + t;
    int v = (i < NN) ? g_cnt[i] : 0;
    if (i < NN) {
        float deg = (float)(v + 1);
        g_dinv[i]  = rsqrtf(deg);
        g_dinv2[i] = 1.0f / deg;
    }
    s[t] = v;
    __syncthreads();
    #pragma unroll
    for (int o = 1; o < SCAN_B; o <<= 1) {
        int x = (t >= o) ? s[t - o] : 0;
        __syncthreads();
        s[t] += x;
        __syncthreads();
    }
    if (i < NN) g_cnt[i] = s[t];
    if (t == SCAN_B - 1) g_bsum[blockIdx.x] = s[t];
}
__global__ __launch_bounds__(SCAN_B) void k_scan3() {
    __shared__ int partial[32];
    __shared__ int pre_s;
    int t = threadIdx.x;
    int v = (t < NSB && t < blockIdx.x) ? g_bsum[t] : 0;
    #pragma unroll
    for (int o = 16; o > 0; o >>= 1) v += __shfl_down_sync(0xffffffffu, v, o);
    if ((t & 31) == 0) partial[t >> 5] = v;
    __syncthreads();
    if (t == 0) {
        int s = 0;
        #pragma unroll
        for (int w = 0; w < SCAN_B / 32; w++) s += partial[w];
        pre_s = s;
    }
    __syncthreads();
    int pre = pre_s;
    int i = blockIdx.x * SCAN_B + t;
    if (i < NN) {
        int incl = g_cnt[i] + pre;
        g_off[i + 1] = incl;
        if (i + 1 < NN) g_cursor[i + 1] = incl;
        if (i == 0) { g_off[0] = 0; g_cursor[0] = 0; }
    }
}
__global__ void k_scatter(const int* __restrict__ src, const int* __restrict__ dst) {
    int e = blockIdx.x * blockDim.x + threadIdx.x;
    if (e < NE) {
        int s = src[e], t = dst[e];
        int p = atomicAdd(&g_cursor[t], 1);
        g_csrc[p] = s;
        g_cw[p]   = g_dinv[s] * g_dinv[t];
    }
}

// ============ tensor-core GEMM: hwb[M,128](bf16) = A @ W, 256 rows/CTA ============
// FUSE=0: A = fp32 input x (3-term split). FUSE=1: A = hbf (bf16, 2-term split).
template <int FUSE>
__global__ __launch_bounds__(512, 1) void k_gemm_mma(
    const void* __restrict__ Ain, const uint4* __restrict__ wp,
    uint32_t* __restrict__ outb, int M)
{
    extern __shared__ char smem[];
    uint4* Wp = reinterpret_cast<uint4*>(smem);
    int tid  = threadIdx.x;
    int wid  = tid >> 5;
    int lane = tid & 31;
    int m0   = blockIdx.x * 256;

    #pragma unroll
    for (int i = 0; i < 8; i++) {
        int idx = tid + i * 512;           // 4096 uint4
        int n = idx >> 5, r = idx & 31;
        Wp[n * WPAD + r] = wp[idx];
    }
    __syncthreads();

    int fr = lane >> 2;                    // 0..7
    int q  = lane & 3;                     // 0..3
    int r0 = m0 + wid * 16 + fr;
    int r1 = r0 + 8;
    bool ok0 = r0 < M, ok1 = r1 < M;

    float acc[16][4];
    #pragma unroll
    for (int ni = 0; ni < 16; ni++)
        #pragma unroll
        for (int p = 0; p < 4; p++) acc[ni][p] = 0.f;

    #pragma unroll
    for (int kk = 0; kk < 8; kk++) {
        int kw = kk * 8 + q;
        uint32_t ah[4], al[4];
        if (FUSE) {
            const uint32_t* H = reinterpret_cast<const uint32_t*>(Ain);
            ah[0] = ok0 ? H[(size_t)r0 * 64 + kw]     : 0u;
            ah[2] = ok0 ? H[(size_t)r0 * 64 + kw + 4] : 0u;
            ah[1] = ok1 ? H[(size_t)r1 * 64 + kw]     : 0u;
            ah[3] = ok1 ? H[(size_t)r1 * 64 + kw + 4] : 0u;
        } else {
            const float2* A2 = reinterpret_cast<const float2*>(Ain);
            float2 v00 = make_float2(0.f, 0.f), v01 = v00, v10 = v00, v11 = v00;
            if (ok0) { v00 = A2[(size_t)r0 * 64 + kw]; v01 = A2[(size_t)r0 * 64 + kw + 4]; }
            if (ok1) { v10 = A2[(size_t)r1 * 64 + kw]; v11 = A2[(size_t)r1 * 64 + kw + 4]; }
            __nv_bfloat162 h; float2 f;
            h = __float22bfloat162_rn(v00); f = __bfloat1622float2(h);
            ah[0] = *reinterpret_cast<uint32_t*>(&h); al[0] = bf2_of(v00.x - f.x, v00.y - f.y);
            h = __float22bfloat162_rn(v10); f = __bfloat1622float2(h);
            ah[1] = *reinterpret_cast<uint32_t*>(&h); al[1] = bf2_of(v10.x - f.x, v10.y - f.y);
            h = __float22bfloat162_rn(v01); f = __bfloat1622float2(h);
            ah[2] = *reinterpret_cast<uint32_t*>(&h); al[2] = bf2_of(v01.x - f.x, v01.y - f.y);
            h = __float22bfloat162_rn(v11); f = __bfloat1622float2(h);
            ah[3] = *reinterpret_cast<uint32_t*>(&h); al[3] = bf2_of(v11.x - f.x, v11.y - f.y);
        }
        #pragma unroll
        for (int ni = 0; ni < 16; ni++) {
            int n = ni * 8 + fr;
            uint4 b = Wp[n * WPAD + kk * 4 + q];
            mma_bf16(acc[ni], ah[0], ah[1], ah[2], ah[3], b.x, b.y);      // A_hi * W_hi
            mma_bf16(acc[ni], ah[0], ah[1], ah[2], ah[3], b.z, b.w);      // A_hi * W_lo
            if (!FUSE)
                mma_bf16(acc[ni], al[0], al[1], al[2], al[3], b.x, b.y);  // A_lo * W_hi
        }
    }

    #pragma unroll
    for (int ni = 0; ni < 16; ni++) {
        int cw = ni * 4 + q;
        if (ok0) outb[(size_t)r0 * 64 + cw] = bf2_of(acc[ni][0], acc[ni][1]);
        if (ok1) outb[(size_t)r1 * 64 + cw] = bf2_of(acc[ni][2], acc[ni][3]);
    }
}

// ---- CSR aggregation, 2 warps per node (64 features each), 4-way unrolled ----
__global__ __launch_bounds__(256) void k_agg(const uint32_t* __restrict__ hwb,
                                             const float* __restrict__ bias,
                                             uint32_t* __restrict__ hbf)
{
    int gid  = blockIdx.x * blockDim.x + threadIdx.x;
    int unit = gid >> 5;                  // 2 units per node
    int n    = unit >> 1;
    int half = unit & 1;
    int lane = threadIdx.x & 31;
    if (n >= NN) return;
    int fw = half * 32 + lane;            // uint32 word index within 64-word row

    uint32_t sv = __ldg(&hwb[(size_t)n * 64 + fw]);
    float2 s = bf2f(sv);
    float w = g_dinv2[n];
    float a0 = s.x * w, a1 = s.y * w;
    int i = g_off[n], end = g_off[n + 1];

    for (; i + 4 <= end; i += 4) {
        int   s0i = g_csrc[i],     s1i = g_csrc[i + 1];
        int   s2i = g_csrc[i + 2], s3i = g_csrc[i + 3];
        float w0 = g_cw[i],     w1 = g_cw[i + 1];
        float w2 = g_cw[i + 2], w3 = g_cw[i + 3];
        uint32_t v0 = __ldg(&hwb[(size_t)s0i * 64 + fw]);
        uint32_t v1 = __ldg(&hwb[(size_t)s1i * 64 + fw]);
        uint32_t v2 = __ldg(&hwb[(size_t)s2i * 64 + fw]);
        uint32_t v3 = __ldg(&hwb[(size_t)s3i * 64 + fw]);
        float2 f;
        f = bf2f(v0); a0 = fmaf(w0, f.x, a0); a1 = fmaf(w0, f.y, a1);
        f = bf2f(v1); a0 = fmaf(w1, f.x, a0); a1 = fmaf(w1, f.y, a1);
        f = bf2f(v2); a0 = fmaf(w2, f.x, a0); a1 = fmaf(w2, f.y, a1);
        f = bf2f(v3); a0 = fmaf(w3, f.x, a0); a1 = fmaf(w3, f.y, a1);
    }
    for (; i < end; i++) {
        int   sn = g_csrc[i];
        float we = g_cw[i];
        uint32_t v = __ldg(&hwb[(size_t)sn * 64 + fw]);
        float2 f = bf2f(v);
        a0 = fmaf(we, f.x, a0);
        a1 = fmaf(we, f.y, a1);
    }
    float2 b2 = reinterpret_cast<const float2*>(bias)[fw];
    hbf[(size_t)n * 64 + fw] = bf2_of(fmaxf(a0 + b2.x, 0.f), fmaxf(a1 + b2.y, 0.f));
}

// ---------------- fused pool + MLP head: one block per graph ----------------
__global__ void k_pool_head(const uint32_t* __restrict__ hp,
                            const float* __restrict__ W1, const float* __restrict__ b1,
                            const float* __restrict__ W2, const float* __restrict__ b2,
                            const float* __restrict__ W3, const float* __restrict__ b3,
                            float* __restrict__ out)
{
    __shared__ float buf[128];
    __shared__ float partial[4];
    int g = blockIdx.x, c = threadIdx.x;
    int n0 = g_goff[g], n1 = g_goff[g + 1];
    int  wsel = c >> 1;
    bool hi   = c & 1;
    float acc = 0.f;
    for (int n = n0; n < n1; n++) {
        float2 hl = bf2f(hp[(size_t)n * 64 + wsel]);
        acc += hi ? hl.y : hl.x;
    }
    buf[c] = acc;
    __syncthreads();
    acc = b1[c];
    #pragma unroll 8
    for (int k = 0; k < 128; k++)
        acc = fmaf(buf[k], W1[k * 128 + c], acc);
    float z1 = fmaxf(acc, 0.f);
    __syncthreads();
    buf[c] = z1;
    __syncthreads();
    acc = b2[c];
    #pragma unroll 8
    for (int k = 0; k < 128; k++)
        acc = fmaf(buf[k], W2[k * 128 + c], acc);
    float z2 = fmaxf(acc, 0.f);
    float v = z2 * W3[c];
    #pragma unroll
    for (int o = 16; o > 0; o >>= 1) v += __shfl_down_sync(0xffffffffu, v, o);
    if ((c & 31) == 0) partial[c >> 5] = v;
    __syncthreads();
    if (c == 0) {
        float s = partial[0] + partial[1] + partial[2] + partial[3] + b3[0];
        out[g] = 1.f / (1.f + expf(-s));
    }
}

// ---------------- launch ----------------
extern "C" void kernel_launch(void* const* d_in, const int* in_sizes, int n_in,
                              void* d_out, int out_size)
{
    const float* x     = (const float*)d_in[0];
    const int*   ei    = (const int*)d_in[1];     // int32 (JAX x64 disabled)
    const int*   src   = ei;
    const int*   dst   = ei + NE;
    const int*   batch = (const int*)d_in[2];
    const float* convW = (const float*)d_in[3];
    const float* convB = (const float*)d_in[4];
    const float* W1    = (const float*)d_in[5];
    const float* b1    = (const float*)d_in[6];
    const float* W2    = (const float*)d_in[7];
    const float* b2    = (const float*)d_in[8];
    const float* W3    = (const float*)d_in[9];
    const float* b3    = (const float*)d_in[10];
    float* out = (float*)d_out;

    uint2 *hwb, *hbf;  uint4* wpk;
    cudaGetSymbolAddress((void**)&hwb, g_hwb);
    cudaGetSymbolAddress((void**)&hbf, g_hbf);
    cudaGetSymbolAddress((void**)&wpk, g_wpack);

    static cudaStream_t s2;
    static cudaEvent_t evFork, evJoin;
    static bool once = false;
    if (!once) {
        cudaFuncSetAttribute(k_gemm_mma<0>, cudaFuncAttributeMaxDynamicSharedMemorySize, SMEM_MMA);
        cudaFuncSetAttribute(k_gemm_mma<1>, cudaFuncAttributeMaxDynamicSharedMemorySize, SMEM_MMA);
        cudaStreamCreateWithFlags(&s2, cudaStreamNonBlocking);
        cudaEventCreateWithFlags(&evFork, cudaEventDisableTiming);
        cudaEventCreateWithFlags(&evJoin, cudaEventDisableTiming);
        once = true;
    }

    // ---- fork: CSR build (+goff) on side stream, W pack + gemm0 on main ----
    cudaEventRecord(evFork, 0);
    cudaStreamWaitEvent(s2, evFork, 0);

    k_cntzero<<<(NN + 255) / 256, 256, 0, s2>>>();
    k_cnt    <<<(NE + 255) / 256, 256, 0, s2>>>(dst);
    k_goff   <<<(NN + 256) / 256, 256, 0, s2>>>(batch);
    k_scan1  <<<NSB, SCAN_B, 0, s2>>>();
    k_scan3  <<<NSB, SCAN_B, 0, s2>>>();
    k_scatter<<<(NE + 255) / 256, 256, 0, s2>>>(src, dst);
    cudaEventRecord(evJoin, s2);

    uint32_t* hwb32 = reinterpret_cast<uint32_t*>(hwb);
    uint32_t* hbf32 = reinterpret_cast<uint32_t*>(hbf);
    k_wpack<<<64, 256>>>(convW);
    k_gemm_mma<0><<<NTILES, 512, SMEM_MMA>>>(x, wpk, hwb32, NN);

    // ---- join, then the remaining dependent chain ----
    cudaStreamWaitEvent(0, evJoin, 0);
    k_agg<<<(NN * 64 + 255) / 256, 256>>>(hwb32, convB, hbf32);
    for (int l = 1; l < 4; l++) {
        k_gemm_mma<1><<<NTILES, 512, SMEM_MMA>>>(hbf, wpk + (size_t)l * 4096, hwb32, NN);
        k_agg<<<(NN * 64 + 255) / 256, 256>>>(hwb32, convB + (size_t)l * DD, hbf32);
    }

    // ---- fused pool + MLP head ----
    k_pool_head<<<NG, 128>>>(hbf32, W1, b1, W2, b2, W3, b3, out);
}

// round 15
// speedup vs baseline: 1.2398x; 1.2398x over previous
#include <cuda_runtime.h>
#include <cuda_bf16.h>
#include <math.h>
#include <cstdint>

#define NN   100000
#define NE   640000
#define DD   128
#define NG   512
#define SCAN_B 1024
#define NSB  ((NN + SCAN_B - 1) / SCAN_B)   // 98 scan blocks
#define NTILES ((NN + 255) / 256)           // 391 (256 rows per CTA)

// ---------------- scratch (no allocations allowed) ----------------
__device__ uint2 g_hwb[(size_t)NN * 32];    // h@W in bf16x2 (25.6MB)
__device__ uint2 g_hbf[(size_t)NN * 32];    // relu(agg+b) in bf16x2 (25.6MB)
__device__ float g_dinv[NN];
__device__ float g_dinv2[NN];
__device__ int   g_cnt [NN];
__device__ int   g_off [NN + 1];
__device__ int   g_cursor[NN];
__device__ int2  g_cse [NE];                // interleaved {src, weight-bits}
__device__ int   g_bsum[NSB];
__device__ int   g_goff[NG + 1];            // per-graph node ranges (batch sorted)
// packed W fragments: [layer][n(128)][kk(8)][q(4)] uint4 = {hi@kb, hi@kb+4, lo@kb, lo@kb+4}
__device__ uint4 g_wpack[4 * 128 * 8 * 4];

// ---------------- smem layout for MMA GEMM ----------------
#define WPAD 36                          // uint4 per n-row in smem (padded from 32)
#define SMEM_MMA (128 * WPAD * 16)       // 73728

__device__ __forceinline__ void mma_bf16(float c[4], uint32_t a0, uint32_t a1,
                                         uint32_t a2, uint32_t a3,
                                         uint32_t b0, uint32_t b1) {
    asm volatile(
        "mma.sync.aligned.m16n8k16.row.col.f32.bf16.bf16.f32 "
        "{%0,%1,%2,%3}, {%4,%5,%6,%7}, {%8,%9}, {%0,%1,%2,%3};"
        : "+f"(c[0]), "+f"(c[1]), "+f"(c[2]), "+f"(c[3])
        : "r"(a0), "r"(a1), "r"(a2), "r"(a3), "r"(b0), "r"(b1));
}

__device__ __forceinline__ uint32_t bf2_of(float a, float b) {
    __nv_bfloat162 t = __float22bfloat162_rn(make_float2(a, b));
    return *reinterpret_cast<uint32_t*>(&t);
}
__device__ __forceinline__ float2 bf2f(uint32_t u) {
    __nv_bfloat162 h = *reinterpret_cast<__nv_bfloat162*>(&u);
    return __bfloat1622float2(h);
}

// ---------------- main-stream init: W pack ----------------
__global__ void k_wpack(const float* __restrict__ convW) {
    int idx = blockIdx.x * 256 + threadIdx.x;
    if (idx < 16384) {
        int q  = idx & 3;
        int kk = (idx >> 2) & 7;
        int n  = (idx >> 5) & 127;
        int l  = idx >> 12;
        int k0 = kk * 16 + q * 2;
        const float* Wl = convW + (size_t)l * 16384;
        float w00 = Wl[(size_t)(k0    ) * 128 + n], w01 = Wl[(size_t)(k0 + 1) * 128 + n];
        float w10 = Wl[(size_t)(k0 + 8) * 128 + n], w11 = Wl[(size_t)(k0 + 9) * 128 + n];
        __nv_bfloat162 h0 = __float22bfloat162_rn(make_float2(w00, w01));
        __nv_bfloat162 h1 = __float22bfloat162_rn(make_float2(w10, w11));
        float2 f0 = __bfloat1622float2(h0), f1 = __bfloat1622float2(h1);
        uint4 v;
        v.x = *reinterpret_cast<uint32_t*>(&h0);
        v.y = *reinterpret_cast<uint32_t*>(&h1);
        v.z = bf2_of(w00 - f0.x, w01 - f0.y);
        v.w = bf2_of(w10 - f1.x, w11 - f1.y);
        g_wpack[idx] = v;
    }
}

// ---------------- side-stream CSR build + graph offsets ----------------
__global__ void k_cnt(const int* __restrict__ dst) {
    int e = blockIdx.x * blockDim.x + threadIdx.x;
    if (e < NE) atomicAdd(&g_cnt[dst[e]], 1);
}
// per-graph node ranges from sorted batch
__global__ void k_goff(const int* __restrict__ batch) {
    int n = blockIdx.x * blockDim.x + threadIdx.x;
    if (n > NN) return;
    int glo = (n == 0)  ? 0  : batch[n - 1] + 1;
    int ghi = (n == NN) ? NG : batch[n];
    for (int g = glo; g <= ghi; g++) g_goff[g] = n;
}
__global__ __launch_bounds__(SCAN_B) void k_scan1() {
    __shared__ int s[SCAN_B];
    int t = threadIdx.x;
    int i = blockIdx.x * SCAN_B + t;
    int v = (i < NN) ? g_cnt[i] : 0;
    if (i < NN) {
        float deg = (float)(v + 1);
        g_dinv[i]  = rsqrtf(deg);
        g_dinv2[i] = 1.0f / deg;
    }
    s[t] = v;
    __syncthreads();
    #pragma unroll
    for (int o = 1; o < SCAN_B; o <<= 1) {
        int x = (t >= o) ? s[t - o] : 0;
        __syncthreads();
        s[t] += x;
        __syncthreads();
    }
    if (i < NN) g_cnt[i] = s[t];
    if (t == SCAN_B - 1) g_bsum[blockIdx.x] = s[t];
}
__global__ __launch_bounds__(SCAN_B) void k_scan3() {
    __shared__ int partial[32];
    __shared__ int pre_s;
    int t = threadIdx.x;
    int v = (t < NSB && t < blockIdx.x) ? g_bsum[t] : 0;
    #pragma unroll
    for (int o = 16; o > 0; o >>= 1) v += __shfl_down_sync(0xffffffffu, v, o);
    if ((t & 31) == 0) partial[t >> 5] = v;
    __syncthreads();
    if (t == 0) {
        int s = 0;
        #pragma unroll
        for (int w = 0; w < SCAN_B / 32; w++) s += partial[w];
        pre_s = s;
    }
    __syncthreads();
    int pre = pre_s;
    int i = blockIdx.x * SCAN_B + t;
    if (i < NN) {
        int incl = g_cnt[i] + pre;
        g_off[i + 1] = incl;
        if (i + 1 < NN) g_cursor[i + 1] = incl;
        if (i == 0) { g_off[0] = 0; g_cursor[0] = 0; }
    }
}
__global__ void k_scatter(const int* __restrict__ src, const int* __restrict__ dst) {
    int e = blockIdx.x * blockDim.x + threadIdx.x;
    if (e < NE) {
        int s = src[e], t = dst[e];
        int p = atomicAdd(&g_cursor[t], 1);
        float w = g_dinv[s] * g_dinv[t];
        g_cse[p] = make_int2(s, __float_as_int(w));
    }
}

// ============ tensor-core GEMM: hwb[M,128](bf16) = A @ W, 256 rows/CTA ============
// FUSE=0: A = fp32 input x (3-term split). FUSE=1: A = hbf (bf16, 2-term split).
template <int FUSE>
__global__ __launch_bounds__(512, 1) void k_gemm_mma(
    const void* __restrict__ Ain, const uint4* __restrict__ wp,
    uint32_t* __restrict__ outb, int M)
{
    extern __shared__ char smem[];
    uint4* Wp = reinterpret_cast<uint4*>(smem);
    int tid  = threadIdx.x;
    int wid  = tid >> 5;
    int lane = tid & 31;
    int m0   = blockIdx.x * 256;

    #pragma unroll
    for (int i = 0; i < 8; i++) {
        int idx = tid + i * 512;           // 4096 uint4
        int n = idx >> 5, r = idx & 31;
        Wp[n * WPAD + r] = wp[idx];
    }
    __syncthreads();

    int fr = lane >> 2;                    // 0..7
    int q  = lane & 3;                     // 0..3
    int r0 = m0 + wid * 16 + fr;
    int r1 = r0 + 8;
    bool ok0 = r0 < M, ok1 = r1 < M;

    float acc[16][4];
    #pragma unroll
    for (int ni = 0; ni < 16; ni++)
        #pragma unroll
        for (int p = 0; p < 4; p++) acc[ni][p] = 0.f;

    #pragma unroll
    for (int kk = 0; kk < 8; kk++) {
        int kw = kk * 8 + q;
        uint32_t ah[4], al[4];
        if (FUSE) {
            const uint32_t* H = reinterpret_cast<const uint32_t*>(Ain);
            ah[0] = ok0 ? H[(size_t)r0 * 64 + kw]     : 0u;
            ah[2] = ok0 ? H[(size_t)r0 * 64 + kw + 4] : 0u;
            ah[1] = ok1 ? H[(size_t)r1 * 64 + kw]     : 0u;
            ah[3] = ok1 ? H[(size_t)r1 * 64 + kw + 4] : 0u;
        } else {
            const float2* A2 = reinterpret_cast<const float2*>(Ain);
            float2 v00 = make_float2(0.f, 0.f), v01 = v00, v10 = v00, v11 = v00;
            if (ok0) { v00 = A2[(size_t)r0 * 64 + kw]; v01 = A2[(size_t)r0 * 64 + kw + 4]; }
            if (ok1) { v10 = A2[(size_t)r1 * 64 + kw]; v11 = A2[(size_t)r1 * 64 + kw + 4]; }
            __nv_bfloat162 h; float2 f;
            h = __float22bfloat162_rn(v00); f = __bfloat1622float2(h);
            ah[0] = *reinterpret_cast<uint32_t*>(&h); al[0] = bf2_of(v00.x - f.x, v00.y - f.y);
            h = __float22bfloat162_rn(v10); f = __bfloat1622float2(h);
            ah[1] = *reinterpret_cast<uint32_t*>(&h); al[1] = bf2_of(v10.x - f.x, v10.y - f.y);
            h = __float22bfloat162_rn(v01); f = __bfloat1622float2(h);
            ah[2] = *reinterpret_cast<uint32_t*>(&h); al[2] = bf2_of(v01.x - f.x, v01.y - f.y);
            h = __float22bfloat162_rn(v11); f = __bfloat1622float2(h);
            ah[3] = *reinterpret_cast<uint32_t*>(&h); al[3] = bf2_of(v11.x - f.x, v11.y - f.y);
        }
        #pragma unroll
        for (int ni = 0; ni < 16; ni++) {
            int n = ni * 8 + fr;
            uint4 b = Wp[n * WPAD + kk * 4 + q];
            mma_bf16(acc[ni], ah[0], ah[1], ah[2], ah[3], b.x, b.y);      // A_hi * W_hi
            mma_bf16(acc[ni], ah[0], ah[1], ah[2], ah[3], b.z, b.w);      // A_hi * W_lo
            if (!FUSE)
                mma_bf16(acc[ni], al[0], al[1], al[2], al[3], b.x, b.y);  // A_lo * W_hi
        }
    }

    #pragma unroll
    for (int ni = 0; ni < 16; ni++) {
        int cw = ni * 4 + q;
        if (ok0) outb[(size_t)r0 * 64 + cw] = bf2_of(acc[ni][0], acc[ni][1]);
        if (ok1) outb[(size_t)r1 * 64 + cw] = bf2_of(acc[ni][2], acc[ni][3]);
    }
}

// ---- CSR aggregation, 1 warp/node, 4-way unrolled, interleaved edge stream ----
__global__ __launch_bounds__(256) void k_agg(const uint2* __restrict__ hwb,
                                             const float* __restrict__ bias,
                                             uint2* __restrict__ hbf)
{
    int gid  = blockIdx.x * blockDim.x + threadIdx.x;
    int n    = gid >> 5;
    int lane = threadIdx.x & 31;
    if (n >= NN) return;
    uint2 sv = hwb[(size_t)n * 32 + lane];
    float2 s0 = bf2f(sv.x), s1 = bf2f(sv.y);
    float w = g_dinv2[n];
    float a0 = s0.x * w, a1 = s0.y * w, a2 = s1.x * w, a3 = s1.y * w;
    int i = g_off[n], end = g_off[n + 1];

    for (; i + 4 <= end; i += 4) {
        int2 e0 = g_cse[i],     e1 = g_cse[i + 1];
        int2 e2 = g_cse[i + 2], e3 = g_cse[i + 3];
        float w0 = __int_as_float(e0.y), w1 = __int_as_float(e1.y);
        float w2 = __int_as_float(e2.y), w3 = __int_as_float(e3.y);
        uint2 v0 = __ldg(&hwb[(size_t)e0.x * 32 + lane]);
        uint2 v1 = __ldg(&hwb[(size_t)e1.x * 32 + lane]);
        uint2 v2 = __ldg(&hwb[(size_t)e2.x * 32 + lane]);
        uint2 v3 = __ldg(&hwb[(size_t)e3.x * 32 + lane]);
        float2 f;
        f = bf2f(v0.x); a0 = fmaf(w0, f.x, a0); a1 = fmaf(w0, f.y, a1);
        f = bf2f(v0.y); a2 = fmaf(w0, f.x, a2); a3 = fmaf(w0, f.y, a3);
        f = bf2f(v1.x); a0 = fmaf(w1, f.x, a0); a1 = fmaf(w1, f.y, a1);
        f = bf2f(v1.y); a2 = fmaf(w1, f.x, a2); a3 = fmaf(w1, f.y, a3);
        f = bf2f(v2.x); a0 = fmaf(w2, f.x, a0); a1 = fmaf(w2, f.y, a1);
        f = bf2f(v2.y); a2 = fmaf(w2, f.x, a2); a3 = fmaf(w2, f.y, a3);
        f = bf2f(v3.x); a0 = fmaf(w3, f.x, a0); a1 = fmaf(w3, f.y, a1);
        f = bf2f(v3.y); a2 = fmaf(w3, f.x, a2); a3 = fmaf(w3, f.y, a3);
    }
    for (; i < end; i++) {
        int2 e = g_cse[i];
        float we = __int_as_float(e.y);
        uint2 v  = __ldg(&hwb[(size_t)e.x * 32 + lane]);
        float2 f0 = bf2f(v.x), f1 = bf2f(v.y);
        a0 = fmaf(we, f0.x, a0);
        a1 = fmaf(we, f0.y, a1);
        a2 = fmaf(we, f1.x, a2);
        a3 = fmaf(we, f1.y, a3);
    }
    float4 b4 = reinterpret_cast<const float4*>(bias)[lane];
    uint2 o;
    o.x = bf2_of(fmaxf(a0 + b4.x, 0.f), fmaxf(a1 + b4.y, 0.f));
    o.y = bf2_of(fmaxf(a2 + b4.z, 0.f), fmaxf(a3 + b4.w, 0.f));
    hbf[(size_t)n * 32 + lane] = o;
}

// ---------------- fused pool + MLP head: one block per graph ----------------
__global__ void k_pool_head(const uint32_t* __restrict__ hp,
                            const float* __restrict__ W1, const float* __restrict__ b1,
                            const float* __restrict__ W2, const float* __restrict__ b2,
                            const float* __restrict__ W3, const float* __restrict__ b3,
                            float* __restrict__ out)
{
    __shared__ float buf[128];
    __shared__ float partial[4];
    int g = blockIdx.x, c = threadIdx.x;
    int n0 = g_goff[g], n1 = g_goff[g + 1];
    int  wsel = c >> 1;
    bool hi   = c & 1;
    float acc = 0.f;
    for (int n = n0; n < n1; n++) {
        float2 hl = bf2f(hp[(size_t)n * 64 + wsel]);
        acc += hi ? hl.y : hl.x;
    }
    buf[c] = acc;
    __syncthreads();
    acc = b1[c];
    #pragma unroll 8
    for (int k = 0; k < 128; k++)
        acc = fmaf(buf[k], W1[k * 128 + c], acc);
    float z1 = fmaxf(acc, 0.f);
    __syncthreads();
    buf[c] = z1;
    __syncthreads();
    acc = b2[c];
    #pragma unroll 8
    for (int k = 0; k < 128; k++)
        acc = fmaf(buf[k], W2[k * 128 + c], acc);
    float z2 = fmaxf(acc, 0.f);
    float v = z2 * W3[c];
    #pragma unroll
    for (int o = 16; o > 0; o >>= 1) v += __shfl_down_sync(0xffffffffu, v, o);
    if ((c & 31) == 0) partial[c >> 5] = v;
    __syncthreads();
    if (c == 0) {
        float s = partial[0] + partial[1] + partial[2] + partial[3] + b3[0];
        out[g] = 1.f / (1.f + expf(-s));
    }
}

// ---------------- launch ----------------
extern "C" void kernel_launch(void* const* d_in, const int* in_sizes, int n_in,
                              void* d_out, int out_size)
{
    const float* x     = (const float*)d_in[0];
    const int*   ei    = (const int*)d_in[1];     // int32 (JAX x64 disabled)
    const int*   src   = ei;
    const int*   dst   = ei + NE;
    const int*   batch = (const int*)d_in[2];
    const float* convW = (const float*)d_in[3];
    const float* convB = (const float*)d_in[4];
    const float* W1    = (const float*)d_in[5];
    const float* b1    = (const float*)d_in[6];
    const float* W2    = (const float*)d_in[7];
    const float* b2    = (const float*)d_in[8];
    const float* W3    = (const float*)d_in[9];
    const float* b3    = (const float*)d_in[10];
    float* out = (float*)d_out;

    uint2 *hwb, *hbf;  uint4* wpk;  int* cnt;
    cudaGetSymbolAddress((void**)&hwb, g_hwb);
    cudaGetSymbolAddress((void**)&hbf, g_hbf);
    cudaGetSymbolAddress((void**)&wpk, g_wpack);
    cudaGetSymbolAddress((void**)&cnt, g_cnt);

    static cudaStream_t s2;
    static cudaEvent_t evFork, evJoin;
    static bool once = false;
    if (!once) {
        cudaFuncSetAttribute(k_gemm_mma<0>, cudaFuncAttributeMaxDynamicSharedMemorySize, SMEM_MMA);
        cudaFuncSetAttribute(k_gemm_mma<1>, cudaFuncAttributeMaxDynamicSharedMemorySize, SMEM_MMA);
        cudaStreamCreateWithFlags(&s2, cudaStreamNonBlocking);
        cudaEventCreateWithFlags(&evFork, cudaEventDisableTiming);
        cudaEventCreateWithFlags(&evJoin, cudaEventDisableTiming);
        once = true;
    }

    // ---- fork: CSR build (+goff) on side stream, W pack + gemm0 on main ----
    cudaEventRecord(evFork, 0);
    cudaStreamWaitEvent(s2, evFork, 0);

    cudaMemsetAsync(cnt, 0, NN * sizeof(int), s2);
    k_cnt    <<<(NE + 255) / 256, 256, 0, s2>>>(dst);
    k_goff   <<<(NN + 256) / 256, 256, 0, s2>>>(batch);
    k_scan1  <<<NSB, SCAN_B, 0, s2>>>();
    k_scan3  <<<NSB, SCAN_B, 0, s2>>>();
    k_scatter<<<(NE + 255) / 256, 256, 0, s2>>>(src, dst);
    cudaEventRecord(evJoin, s2);

    uint32_t* hwb32 = reinterpret_cast<uint32_t*>(hwb);
    k_wpack<<<64, 256>>>(convW);
    k_gemm_mma<0><<<NTILES, 512, SMEM_MMA>>>(x, wpk, hwb32, NN);

    // ---- join, then the remaining dependent chain ----
    cudaStreamWaitEvent(0, evJoin, 0);
    k_agg<<<(NN * 32 + 255) / 256, 256>>>(hwb, convB, hbf);
    for (int l = 1; l < 4; l++) {
        k_gemm_mma<1><<<NTILES, 512, SMEM_MMA>>>(hbf, wpk + (size_t)l * 4096, hwb32, NN);
        k_agg<<<(NN * 32 + 255) / 256, 256>>>(hwb, convB + (size_t)l * DD, hbf);
    }

    // ---- fused pool + MLP head ----
    k_pool_head<<<NG, 128>>>(reinterpret_cast<const uint32_t*>(hbf),
                             W1, b1, W2, b2, W3, b3, out);
}

// round 16
// speedup vs baseline: 1.4270x; 1.1510x over previous
#include <cuda_runtime.h>
#include <cuda_fp16.h>
#include <math.h>
#include <cstdint>

#define NN   100000
#define NE   640000
#define DD   128
#define NG   512
#define SCAN_B 1024
#define NSB  ((NN + SCAN_B - 1) / SCAN_B)   // 98 scan blocks
#define NTILES ((NN + 255) / 256)           // 391 (256 rows per CTA)

// ---------------- scratch (no allocations allowed) ----------------
__device__ uint2 g_hwb[(size_t)NN * 32];    // h@W in fp16x2 (25.6MB)
__device__ uint2 g_hbf[(size_t)NN * 32];    // relu(agg+b) in fp16x2 (25.6MB)
__device__ float g_dinv[NN];
__device__ float g_dinv2[NN];
__device__ int   g_cnt [NN];
__device__ int   g_off [NN + 1];
__device__ int   g_cursor[NN];
__device__ int2  g_cse [NE];                // interleaved {src, weight-bits}
__device__ int   g_bsum[NSB];
__device__ int   g_goff[NG + 1];            // per-graph node ranges (batch sorted)
// packed W fragments (fp16): [layer][n(128)][kk(8)][q(4)] uint2 = {W@kb, W@kb+4}
__device__ uint2 g_wpack[4 * 128 * 8 * 4];

// ---------------- smem layout for MMA GEMM ----------------
#define WPAD 36                          // uint2 per n-row in smem (padded from 32)
#define SMEM_MMA (128 * WPAD * 8)        // 36864

__device__ __forceinline__ void mma_fp16(float c[4], uint32_t a0, uint32_t a1,
                                         uint32_t a2, uint32_t a3,
                                         uint32_t b0, uint32_t b1) {
    asm volatile(
        "mma.sync.aligned.m16n8k16.row.col.f32.f16.f16.f32 "
        "{%0,%1,%2,%3}, {%4,%5,%6,%7}, {%8,%9}, {%0,%1,%2,%3};"
        : "+f"(c[0]), "+f"(c[1]), "+f"(c[2]), "+f"(c[3])
        : "r"(a0), "r"(a1), "r"(a2), "r"(a3), "r"(b0), "r"(b1));
}

__device__ __forceinline__ uint32_t h2_of(float a, float b) {
    __half2 t = __float22half2_rn(make_float2(a, b));
    return *reinterpret_cast<uint32_t*>(&t);
}
__device__ __forceinline__ float2 h2f(uint32_t u) {
    __half2 h = *reinterpret_cast<__half2*>(&u);
    return __half22float2(h);
}

// ---------------- main-stream init: W pack (fp16) ----------------
__global__ void k_wpack(const float* __restrict__ convW) {
    int idx = blockIdx.x * 256 + threadIdx.x;
    if (idx < 16384) {
        int q  = idx & 3;
        int kk = (idx >> 2) & 7;
        int n  = (idx >> 5) & 127;
        int l  = idx >> 12;
        int k0 = kk * 16 + q * 2;
        const float* Wl = convW + (size_t)l * 16384;
        float w00 = Wl[(size_t)(k0    ) * 128 + n], w01 = Wl[(size_t)(k0 + 1) * 128 + n];
        float w10 = Wl[(size_t)(k0 + 8) * 128 + n], w11 = Wl[(size_t)(k0 + 9) * 128 + n];
        uint2 v;
        v.x = h2_of(w00, w01);
        v.y = h2_of(w10, w11);
        g_wpack[idx] = v;
    }
}

// ---------------- side-stream CSR build + graph offsets ----------------
__global__ void k_cnt(const int* __restrict__ dst) {
    int e = blockIdx.x * blockDim.x + threadIdx.x;
    if (e < NE) atomicAdd(&g_cnt[dst[e]], 1);
}
__global__ void k_goff(const int* __restrict__ batch) {
    int n = blockIdx.x * blockDim.x + threadIdx.x;
    if (n > NN) return;
    int glo = (n == 0)  ? 0  : batch[n - 1] + 1;
    int ghi = (n == NN) ? NG : batch[n];
    for (int g = glo; g <= ghi; g++) g_goff[g] = n;
}
__global__ __launch_bounds__(SCAN_B) void k_scan1() {
    __shared__ int s[SCAN_B];
    int t = threadIdx.x;
    int i = blockIdx.x * SCAN_B + t;
    int v = (i < NN) ? g_cnt[i] : 0;
    if (i < NN) {
        float deg = (float)(v + 1);
        g_dinv[i]  = rsqrtf(deg);
        g_dinv2[i] = 1.0f / deg;
    }
    s[t] = v;
    __syncthreads();
    #pragma unroll
    for (int o = 1; o < SCAN_B; o <<= 1) {
        int x = (t >= o) ? s[t - o] : 0;
        __syncthreads();
        s[t] += x;
        __syncthreads();
    }
    if (i < NN) g_cnt[i] = s[t];
    if (t == SCAN_B - 1) g_bsum[blockIdx.x] = s[t];
}
__global__ __launch_bounds__(SCAN_B) void k_scan3() {
    __shared__ int partial[32];
    __shared__ int pre_s;
    int t = threadIdx.x;
    int v = (t < NSB && t < blockIdx.x) ? g_bsum[t] : 0;
    #pragma unroll
    for (int o = 16; o > 0; o >>= 1) v += __shfl_down_sync(0xffffffffu, v, o);
    if ((t & 31) == 0) partial[t >> 5] = v;
    __syncthreads();
    if (t == 0) {
        int s = 0;
        #pragma unroll
        for (int w = 0; w < SCAN_B / 32; w++) s += partial[w];
        pre_s = s;
    }
    __syncthreads();
    int pre = pre_s;
    int i = blockIdx.x * SCAN_B + t;
    if (i < NN) {
        int incl = g_cnt[i] + pre;
        g_off[i + 1] = incl;
        if (i + 1 < NN) g_cursor[i + 1] = incl;
        if (i == 0) { g_off[0] = 0; g_cursor[0] = 0; }
    }
}
__global__ void k_scatter(const int* __restrict__ src, const int* __restrict__ dst) {
    int e = blockIdx.x * blockDim.x + threadIdx.x;
    if (e < NE) {
        int s = src[e], t = dst[e];
        int p = atomicAdd(&g_cursor[t], 1);
        float w = g_dinv[s] * g_dinv[t];
        g_cse[p] = make_int2(s, __float_as_int(w));
    }
}

// ============ tensor-core GEMM: hwb[M,128](fp16) = A @ W, 256 rows/CTA ============
// FUSE=0: A = fp32 input x (2-term fp16 hi/lo split). FUSE=1: A = hbf (fp16, 1 term).
template <int FUSE>
__global__ __launch_bounds__(512, 1) void k_gemm_mma(
    const void* __restrict__ Ain, const uint2* __restrict__ wp,
    uint32_t* __restrict__ outb, int M)
{
    extern __shared__ char smem[];
    uint2* Wp = reinterpret_cast<uint2*>(smem);
    int tid  = threadIdx.x;
    int wid  = tid >> 5;
    int lane = tid & 31;
    int m0   = blockIdx.x * 256;

    #pragma unroll
    for (int i = 0; i < 8; i++) {
        int idx = tid + i * 512;           // 4096 uint2
        int n = idx >> 5, r = idx & 31;
        Wp[n * WPAD + r] = wp[idx];
    }
    __syncthreads();

    int fr = lane >> 2;                    // 0..7
    int q  = lane & 3;                     // 0..3
    int r0 = m0 + wid * 16 + fr;
    int r1 = r0 + 8;
    bool ok0 = r0 < M, ok1 = r1 < M;

    float acc[16][4];
    #pragma unroll
    for (int ni = 0; ni < 16; ni++)
        #pragma unroll
        for (int p = 0; p < 4; p++) acc[ni][p] = 0.f;

    #pragma unroll
    for (int kk = 0; kk < 8; kk++) {
        int kw = kk * 8 + q;
        uint32_t ah[4], al[4];
        if (FUSE) {
            const uint32_t* H = reinterpret_cast<const uint32_t*>(Ain);
            ah[0] = ok0 ? H[(size_t)r0 * 64 + kw]     : 0u;
            ah[2] = ok0 ? H[(size_t)r0 * 64 + kw + 4] : 0u;
            ah[1] = ok1 ? H[(size_t)r1 * 64 + kw]     : 0u;
            ah[3] = ok1 ? H[(size_t)r1 * 64 + kw + 4] : 0u;
        } else {
            const float2* A2 = reinterpret_cast<const float2*>(Ain);
            float2 v00 = make_float2(0.f, 0.f), v01 = v00, v10 = v00, v11 = v00;
            if (ok0) { v00 = A2[(size_t)r0 * 64 + kw]; v01 = A2[(size_t)r0 * 64 + kw + 4]; }
            if (ok1) { v10 = A2[(size_t)r1 * 64 + kw]; v11 = A2[(size_t)r1 * 64 + kw + 4]; }
            __half2 h; float2 f;
            h = __float22half2_rn(v00); f = __half22float2(h);
            ah[0] = *reinterpret_cast<uint32_t*>(&h); al[0] = h2_of(v00.x - f.x, v00.y - f.y);
            h = __float22half2_rn(v10); f = __half22float2(h);
            ah[1] = *reinterpret_cast<uint32_t*>(&h); al[1] = h2_of(v10.x - f.x, v10.y - f.y);
            h = __float22half2_rn(v01); f = __half22float2(h);
            ah[2] = *reinterpret_cast<uint32_t*>(&h); al[2] = h2_of(v01.x - f.x, v01.y - f.y);
            h = __float22half2_rn(v11); f = __half22float2(h);
            ah[3] = *reinterpret_cast<uint32_t*>(&h); al[3] = h2_of(v11.x - f.x, v11.y - f.y);
        }
        #pragma unroll
        for (int ni = 0; ni < 16; ni++) {
            int n = ni * 8 + fr;
            uint2 b = Wp[n * WPAD + kk * 4 + q];
            mma_fp16(acc[ni], ah[0], ah[1], ah[2], ah[3], b.x, b.y);      // A_hi * W
            if (!FUSE)
                mma_fp16(acc[ni], al[0], al[1], al[2], al[3], b.x, b.y);  // A_lo * W
        }
    }

    #pragma unroll
    for (int ni = 0; ni < 16; ni++) {
        int cw = ni * 4 + q;
        if (ok0) outb[(size_t)r0 * 64 + cw] = h2_of(acc[ni][0], acc[ni][1]);
        if (ok1) outb[(size_t)r1 * 64 + cw] = h2_of(acc[ni][2], acc[ni][3]);
    }
}

// ---- CSR aggregation, 1 warp/node, 4-way unrolled, interleaved edge stream ----
__global__ __launch_bounds__(256) void k_agg(const uint2* __restrict__ hwb,
                                             const float* __restrict__ bias,
                                             uint2* __restrict__ hbf)
{
    int gid  = blockIdx.x * blockDim.x + threadIdx.x;
    int n    = gid >> 5;
    int lane = threadIdx.x & 31;
    if (n >= NN) return;
    uint2 sv = hwb[(size_t)n * 32 + lane];
    float2 s0 = h2f(sv.x), s1 = h2f(sv.y);
    float w = g_dinv2[n];
    float a0 = s0.x * w, a1 = s0.y * w, a2 = s1.x * w, a3 = s1.y * w;
    int i = g_off[n], end = g_off[n + 1];

    for (; i + 4 <= end; i += 4) {
        int2 e0 = g_cse[i],     e1 = g_cse[i + 1];
        int2 e2 = g_cse[i + 2], e3 = g_cse[i + 3];
        float w0 = __int_as_float(e0.y), w1 = __int_as_float(e1.y);
        float w2 = __int_as_float(e2.y), w3 = __int_as_float(e3.y);
        uint2 v0 = __ldg(&hwb[(size_t)e0.x * 32 + lane]);
        uint2 v1 = __ldg(&hwb[(size_t)e1.x * 32 + lane]);
        uint2 v2 = __ldg(&hwb[(size_t)e2.x * 32 + lane]);
        uint2 v3 = __ldg(&hwb[(size_t)e3.x * 32 + lane]);
        float2 f;
        f = h2f(v0.x); a0 = fmaf(w0, f.x, a0); a1 = fmaf(w0, f.y, a1);
        f = h2f(v0.y); a2 = fmaf(w0, f.x, a2); a3 = fmaf(w0, f.y, a3);
        f = h2f(v1.x); a0 = fmaf(w1, f.x, a0); a1 = fmaf(w1, f.y, a1);
        f = h2f(v1.y); a2 = fmaf(w1, f.x, a2); a3 = fmaf(w1, f.y, a3);
        f = h2f(v2.x); a0 = fmaf(w2, f.x, a0); a1 = fmaf(w2, f.y, a1);
        f = h2f(v2.y); a2 = fmaf(w2, f.x, a2); a3 = fmaf(w2, f.y, a3);
        f = h2f(v3.x); a0 = fmaf(w3, f.x, a0); a1 = fmaf(w3, f.y, a1);
        f = h2f(v3.y); a2 = fmaf(w3, f.x, a2); a3 = fmaf(w3, f.y, a3);
    }
    for (; i < end; i++) {
        int2 e = g_cse[i];
        float we = __int_as_float(e.y);
        uint2 v  = __ldg(&hwb[(size_t)e.x * 32 + lane]);
        float2 f0 = h2f(v.x), f1 = h2f(v.y);
        a0 = fmaf(we, f0.x, a0);
        a1 = fmaf(we, f0.y, a1);
        a2 = fmaf(we, f1.x, a2);
        a3 = fmaf(we, f1.y, a3);
    }
    float4 b4 = reinterpret_cast<const float4*>(bias)[lane];
    uint2 o;
    o.x = h2_of(fmaxf(a0 + b4.x, 0.f), fmaxf(a1 + b4.y, 0.f));
    o.y = h2_of(fmaxf(a2 + b4.z, 0.f), fmaxf(a3 + b4.w, 0.f));
    hbf[(size_t)n * 32 + lane] = o;
}

// ---------------- fused pool + MLP head: one block per graph ----------------
__global__ void k_pool_head(const uint32_t* __restrict__ hp,
                            const float* __restrict__ W1, const float* __restrict__ b1,
                            const float* __restrict__ W2, const float* __restrict__ b2,
                            const float* __restrict__ W3, const float* __restrict__ b3,
                            float* __restrict__ out)
{
    __shared__ float buf[128];
    __shared__ float partial[4];
    int g = blockIdx.x, c = threadIdx.x;
    int n0 = g_goff[g], n1 = g_goff[g + 1];
    int  wsel = c >> 1;
    bool hi   = c & 1;
    float acc = 0.f;
    for (int n = n0; n < n1; n++) {
        float2 hl = h2f(hp[(size_t)n * 64 + wsel]);
        acc += hi ? hl.y : hl.x;
    }
    buf[c] = acc;
    __syncthreads();
    acc = b1[c];
    #pragma unroll 8
    for (int k = 0; k < 128; k++)
        acc = fmaf(buf[k], W1[k * 128 + c], acc);
    float z1 = fmaxf(acc, 0.f);
    __syncthreads();
    buf[c] = z1;
    __syncthreads();
    acc = b2[c];
    #pragma unroll 8
    for (int k = 0; k < 128; k++)
        acc = fmaf(buf[k], W2[k * 128 + c], acc);
    float z2 = fmaxf(acc, 0.f);
    float v = z2 * W3[c];
    #pragma unroll
    for (int o = 16; o > 0; o >>= 1) v += __shfl_down_sync(0xffffffffu, v, o);
    if ((c & 31) == 0) partial[c >> 5] = v;
    __syncthreads();
    if (c == 0) {
        float s = partial[0] + partial[1] + partial[2] + partial[3] + b3[0];
        out[g] = 1.f / (1.f + expf(-s));
    }
}

// ---------------- launch ----------------
extern "C" void kernel_launch(void* const* d_in, const int* in_sizes, int n_in,
                              void* d_out, int out_size)
{
    const float* x     = (const float*)d_in[0];
    const int*   ei    = (const int*)d_in[1];     // int32 (JAX x64 disabled)
    const int*   src   = ei;
    const int*   dst   = ei + NE;
    const int*   batch = (const int*)d_in[2];
    const float* convW = (const float*)d_in[3];
    const float* convB = (const float*)d_in[4];
    const float* W1    = (const float*)d_in[5];
    const float* b1    = (const float*)d_in[6];
    const float* W2    = (const float*)d_in[7];
    const float* b2    = (const float*)d_in[8];
    const float* W3    = (const float*)d_in[9];
    const float* b3    = (const float*)d_in[10];
    float* out = (float*)d_out;

    uint2 *hwb, *hbf, *wpk;  int* cnt;
    cudaGetSymbolAddress((void**)&hwb, g_hwb);
    cudaGetSymbolAddress((void**)&hbf, g_hbf);
    cudaGetSymbolAddress((void**)&wpk, g_wpack);
    cudaGetSymbolAddress((void**)&cnt, g_cnt);

    static cudaStream_t s2;
    static cudaEvent_t evFork, evJoin;
    static bool once = false;
    if (!once) {
        cudaFuncSetAttribute(k_gemm_mma<0>, cudaFuncAttributeMaxDynamicSharedMemorySize, SMEM_MMA);
        cudaFuncSetAttribute(k_gemm_mma<1>, cudaFuncAttributeMaxDynamicSharedMemorySize, SMEM_MMA);
        cudaStreamCreateWithFlags(&s2, cudaStreamNonBlocking);
        cudaEventCreateWithFlags(&evFork, cudaEventDisableTiming);
        cudaEventCreateWithFlags(&evJoin, cudaEventDisableTiming);
        once = true;
    }

    // ---- fork: CSR build (+goff) on side stream, W pack + gemm0 on main ----
    cudaEventRecord(evFork, 0);
    cudaStreamWaitEvent(s2, evFork, 0);

    cudaMemsetAsync(cnt, 0, NN * sizeof(int), s2);
    k_cnt    <<<(NE + 255) / 256, 256, 0, s2>>>(dst);
    k_goff   <<<(NN + 256) / 256, 256, 0, s2>>>(batch);
    k_scan1  <<<NSB, SCAN_B, 0, s2>>>();
    k_scan3  <<<NSB, SCAN_B, 0, s2>>>();
    k_scatter<<<(NE + 255) / 256, 256, 0, s2>>>(src, dst);
    cudaEventRecord(evJoin, s2);

    uint32_t* hwb32 = reinterpret_cast<uint32_t*>(hwb);
    k_wpack<<<64, 256>>>(convW);
    k_gemm_mma<0><<<NTILES, 512, SMEM_MMA>>>(x, wpk, hwb32, NN);

    // ---- join, then the remaining dependent chain ----
    cudaStreamWaitEvent(0, evJoin, 0);
    k_agg<<<(NN * 32 + 255) / 256, 256>>>(hwb, convB, hbf);
    for (int l = 1; l < 4; l++) {
        k_gemm_mma<1><<<NTILES, 512, SMEM_MMA>>>(hbf, wpk + (size_t)l * 4096, hwb32, NN);
        k_agg<<<(NN * 32 + 255) / 256, 256>>>(hwb, convB + (size_t)l * DD, hbf);
    }

    // ---- fused pool + MLP head ----
    k_pool_head<<<NG, 128>>>(reinterpret_cast<const uint32_t*>(hbf),
                             W1, b1, W2, b2, W3, b3, out);
}